// round 14
// baseline (speedup 1.0000x reference)
#include <cuda_runtime.h>
#include <math_constants.h>
#include <cstdint>

#define BB 64
#define CC 256
#define HW 4096
#define CS 64
#define NC 8
#define CPB 8          // channels per block in k_stat
#define CH_BYTES 16384 // HW * 4 bytes

// ---- scratch (no allocations allowed) ----
__device__ float g_mean[BB * CC];
__device__ float g_min[BB * CC];
__device__ float g_max[BB * CC];
__device__ float g_scale[BB * CC];
__device__ float g_smin[BB];
__device__ float g_smax[BB];
__device__ float g_s[BB];
__device__ float g_z[BB];

// ---- minimal PTX helpers (sm_90+/sm_103a) ----
static __device__ __forceinline__ uint32_t saddr(const void* p) {
    return (uint32_t)__cvta_generic_to_shared(p);
}
static __device__ __forceinline__ void mb_init(uint32_t mbar, uint32_t cnt) {
    asm volatile("mbarrier.init.shared.b64 [%0], %1;" :: "r"(mbar), "r"(cnt) : "memory");
}
static __device__ __forceinline__ void mb_expect_tx(uint32_t mbar, uint32_t bytes) {
    asm volatile("mbarrier.arrive.expect_tx.shared.b64 _, [%0], %1;"
                 :: "r"(mbar), "r"(bytes) : "memory");
}
static __device__ __forceinline__ void tma_bulk_g2s(uint32_t dst, const void* src,
                                                    uint32_t bytes, uint32_t mbar) {
    asm volatile(
        "cp.async.bulk.shared::cluster.global.mbarrier::complete_tx::bytes "
        "[%0], [%1], %2, [%3];"
        :: "r"(dst), "l"(src), "r"(bytes), "r"(mbar) : "memory");
}
static __device__ __forceinline__ void mb_wait(uint32_t mbar, uint32_t parity) {
    asm volatile(
        "{\n\t"
        ".reg .pred P;\n\t"
        "WL%=:\n\t"
        "mbarrier.try_wait.parity.acquire.cta.shared::cta.b64 P, [%0], %1, 0x989680;\n\t"
        "@P bra WD%=;\n\t"
        "bra WL%=;\n\t"
        "WD%=:\n\t"
        "}"
        :: "r"(mbar), "r"(parity) : "memory");
}
static __device__ __forceinline__ void fence_async_shared() {
    asm volatile("fence.proxy.async.shared::cta;" ::: "memory");
}

// ------------------------------------------------------------------
// Kernel 1: per-(b,c) mean/min/max via TMA bulk double-buffer.
// Block = 256 threads, CPB=8 channels of 16KB each, 2-stage pipeline:
// TMA prefetches 2 channels ahead while threads reduce from smem.
// ------------------------------------------------------------------
__global__ void __launch_bounds__(256) k_stat(const float* __restrict__ x) {
    __shared__ alignas(1024) float4 buf[2][HW / 4];  // 2 x 16KB
    __shared__ uint64_t mbar_sto[2];
    __shared__ float sh_s[8], sh_mn[8], sh_mx[8];

    int t = threadIdx.x;
    uint32_t mb0 = saddr(&mbar_sto[0]);
    uint32_t mb1 = saddr(&mbar_sto[1]);
    uint32_t db0 = saddr(&buf[0][0]);
    uint32_t db1 = saddr(&buf[1][0]);

    if (t == 0) {
        mb_init(mb0, 1);
        mb_init(mb1, 1);
        fence_async_shared();
    }
    __syncthreads();

    int ch0 = blockIdx.x * CPB;
    const char* gbase = (const char*)(x) + (size_t)ch0 * CH_BYTES;

    if (t == 0) {
        mb_expect_tx(mb0, CH_BYTES);
        tma_bulk_g2s(db0, gbase + 0 * (size_t)CH_BYTES, CH_BYTES, mb0);
        mb_expect_tx(mb1, CH_BYTES);
        tma_bulk_g2s(db1, gbase + 1 * (size_t)CH_BYTES, CH_BYTES, mb1);
    }

    int w = t >> 5, l = t & 31;
    for (int c = 0; c < CPB; c++) {
        uint32_t mb = (c & 1) ? mb1 : mb0;
        mb_wait(mb, (c >> 1) & 1);

        const float4* p = buf[c & 1];
        float s = 0.f, mn = CUDART_INF_F, mx = -CUDART_INF_F;
#pragma unroll
        for (int i = 0; i < 4; i++) {
            float4 v = p[t + i * 256];
            s += (v.x + v.y) + (v.z + v.w);
            mn = fminf(mn, fminf(fminf(v.x, v.y), fminf(v.z, v.w)));
            mx = fmaxf(mx, fmaxf(fmaxf(v.x, v.y), fmaxf(v.z, v.w)));
        }
#pragma unroll
        for (int o = 16; o > 0; o >>= 1) {
            s  += __shfl_down_sync(0xffffffffu, s, o);
            mn = fminf(mn, __shfl_down_sync(0xffffffffu, mn, o));
            mx = fmaxf(mx, __shfl_down_sync(0xffffffffu, mx, o));
        }
        if (l == 0) { sh_s[w] = s; sh_mn[w] = mn; sh_mx[w] = mx; }
        __syncthreads();
        if (t == 0) {
            float S = 0.f, MN = CUDART_INF_F, MX = -CUDART_INF_F;
#pragma unroll
            for (int i = 0; i < 8; i++) {
                S += sh_s[i];
                MN = fminf(MN, sh_mn[i]);
                MX = fmaxf(MX, sh_mx[i]);
            }
            g_mean[ch0 + c] = S * (1.0f / HW);
            g_min[ch0 + c]  = MN;
            g_max[ch0 + c]  = MX;
        }
        __syncthreads();   // buffer fully consumed + sh_* read done
        if (t == 0 && c + 2 < CPB) {
            mb_expect_tx(mb, CH_BYTES);
            tma_bulk_g2s((c & 1) ? db1 : db0,
                         gbase + (size_t)(c + 2) * CH_BYTES, CH_BYTES, mb);
        }
    }
}

// ------------------------------------------------------------------
// Kernel 2: SE MLP + hardsigmoid scale per (b,c), and per-sample
// min/max of out = scale*x (scale>=0 => min(scale*x)=scale*min(x)).
// ------------------------------------------------------------------
__global__ void k_se(const float* __restrict__ w1, const float* __restrict__ b1,
                     const float* __restrict__ w2, const float* __restrict__ b2) {
    int b = blockIdx.x, t = threadIdx.x;
    __shared__ float pooled[CC];
    __shared__ float hsh[CS];

    pooled[t] = g_mean[b * CC + t];
    __syncthreads();

    if (t < CS) {
        float acc = b1[t];
#pragma unroll 8
        for (int c = 0; c < CC; c++) acc = fmaf(pooled[c], w1[t * CC + c], acc);
        hsh[t] = fmaxf(acc, 0.f);
    }
    __syncthreads();

    float acc = b2[t];
#pragma unroll 8
    for (int s = 0; s < CS; s++) acc = fmaf(hsh[s], w2[t * CS + s], acc);
    float sc = fminf(fmaxf(acc / 6.0f + 0.5f, 0.f), 1.f);   // hardsigmoid
    g_scale[b * CC + t] = sc;

    float mn = sc * g_min[b * CC + t];
    float mx = sc * g_max[b * CC + t];
#pragma unroll
    for (int o = 16; o > 0; o >>= 1) {
        mn = fminf(mn, __shfl_down_sync(0xffffffffu, mn, o));
        mx = fmaxf(mx, __shfl_down_sync(0xffffffffu, mx, o));
    }
    __shared__ float sh_mn[8], sh_mx[8];
    int w = t >> 5, l = t & 31;
    if (l == 0) { sh_mn[w] = mn; sh_mx[w] = mx; }
    __syncthreads();
    if (t == 0) {
        float MN = CUDART_INF_F, MX = -CUDART_INF_F;
#pragma unroll
        for (int i = 0; i < 8; i++) { MN = fminf(MN, sh_mn[i]); MX = fmaxf(MX, sh_mx[i]); }
        g_smin[b] = MN;
        g_smax[b] = MX;
    }
}

// ------------------------------------------------------------------
// Kernel 3: per-cluster segment min/max + EMA + quant params.
// Staged through shared memory (fast version from R12).
// ------------------------------------------------------------------
__global__ void k_cluster(const float* __restrict__ act_range,
                          const int* __restrict__ scl) {
    __shared__ float smn[BB], smx[BB];
    __shared__ int   scls[BB];
    __shared__ float cs[NC], cz[NC];
    int t = threadIdx.x;   // 64 threads

    smn[t]  = g_smin[t];
    smx[t]  = g_smax[t];
    scls[t] = scl[t];
    __syncthreads();

    if (t < NC) {
        float mn = CUDART_INF_F, mx = -CUDART_INF_F;  // JAX segment identities
#pragma unroll
        for (int b = 0; b < BB; b++) {
            if (scls[b] == t) {
                mn = fminf(mn, smn[b]);
                mx = fmaxf(mx, smx[b]);
            }
        }
        float nm = act_range[t * 2 + 0] * 0.995f + mn * 0.005f;
        float nx = act_range[t * 2 + 1] * 0.995f + mx * 0.005f;
        float s = (nx - nm) / 255.0f;
        float z = -rintf(__fdiv_rn(nm, s));
        cs[t] = s;
        cz[t] = z;
    }
    __syncthreads();
    {
        int k = scls[t];
        g_s[t] = cs[k];
        g_z[t] = cz[k];
    }
}

// ------------------------------------------------------------------
// Kernel 4: streaming fake-quant — measured-optimal config
// (regs 21, occ ~80%, ~85us @ 72% DRAM). Unchanged from R12.
// ------------------------------------------------------------------
__global__ void __launch_bounds__(256) k_quant(const float* __restrict__ x,
                                               float* __restrict__ out) {
    int i = blockIdx.x * blockDim.x + threadIdx.x;  // float4 index
    int bc = i >> 10;        // HW/4 = 1024 float4 per channel
    int b  = bc >> 8;        // CC = 256 channels per sample
    float sc = __ldg(&g_scale[bc]);
    float s  = __ldg(&g_s[b]);
    float z  = __ldg(&g_z[b]);

    float4 v = reinterpret_cast<const float4*>(x)[i];
    float4 r;
#define QUANT(a, o)                                                          \
    {                                                                        \
        float ov = sc * (a);                                                 \
        float q  = fminf(fmaxf(rintf(__fdiv_rn(ov, s) + z), 0.f), 255.f);    \
        (o) = (q - z) * s;                                                   \
    }
    QUANT(v.x, r.x)
    QUANT(v.y, r.y)
    QUANT(v.z, r.z)
    QUANT(v.w, r.w)
#undef QUANT
    __stcs(reinterpret_cast<float4*>(out) + i, r);
}

extern "C" void kernel_launch(void* const* d_in, const int* in_sizes, int n_in,
                              void* d_out, int out_size) {
    const float* x         = (const float*)d_in[0];
    const float* w1        = (const float*)d_in[1];
    const float* b1        = (const float*)d_in[2];
    const float* w2        = (const float*)d_in[3];
    const float* b2        = (const float*)d_in[4];
    const float* act_range = (const float*)d_in[5];
    const int*   scl       = (const int*)d_in[6];
    float* out = (float*)d_out;

    // k_stat: TMA double-buffered, 8 channels/block
    k_stat<<<(BB * CC) / CPB, 256>>>(x);
    k_se<<<BB, 256>>>(w1, b1, w2, b2);
    k_cluster<<<1, 64>>>(act_range, scl);
    k_quant<<<(BB * CC * HW / 4) / 256, 256>>>(x, out);
}

// round 16
// speedup vs baseline: 1.0446x; 1.0446x over previous
#include <cuda_runtime.h>
#include <math_constants.h>

#define BB 64
#define CC 256
#define HW 4096
#define CS 64
#define NC 8

// ---- scratch (no allocations allowed) ----
__device__ float g_mean[BB * CC];
__device__ float g_min[BB * CC];
__device__ float g_max[BB * CC];
__device__ float g_scale[BB * CC];
__device__ float g_smin[BB];
__device__ float g_smax[BB];
__device__ float g_s[BB];
__device__ float g_z[BB];

// ------------------------------------------------------------------
// Kernel 1: per-(b,c) mean / min / max. Warp-per-channel, batches of
// 4 LDG.128 (R9 config — best measured stat at ~64us).
// ------------------------------------------------------------------
__global__ void __launch_bounds__(256) k_stat(const float* __restrict__ x) {
    int gw   = (blockIdx.x * blockDim.x + threadIdx.x) >> 5;  // global warp = (b,c)
    int lane = threadIdx.x & 31;
    const float4* xp = reinterpret_cast<const float4*>(x) + (size_t)gw * (HW / 4) + lane;

    float s0 = 0.f, s1 = 0.f, s2 = 0.f, s3 = 0.f;
    float mn = CUDART_INF_F, mx = -CUDART_INF_F;
#pragma unroll 1
    for (int i = 0; i < 8; i++) {
        const float4* p = xp + i * 128;
        float4 a = __ldg(p);
        float4 b = __ldg(p + 32);
        float4 c = __ldg(p + 64);
        float4 d = __ldg(p + 96);
        s0 += (a.x + a.y) + (a.z + a.w);
        s1 += (b.x + b.y) + (b.z + b.w);
        s2 += (c.x + c.y) + (c.z + c.w);
        s3 += (d.x + d.y) + (d.z + d.w);
        mn = fminf(mn, fminf(fminf(a.x, a.y), fminf(a.z, a.w)));
        mn = fminf(mn, fminf(fminf(b.x, b.y), fminf(b.z, b.w)));
        mn = fminf(mn, fminf(fminf(c.x, c.y), fminf(c.z, c.w)));
        mn = fminf(mn, fminf(fminf(d.x, d.y), fminf(d.z, d.w)));
        mx = fmaxf(mx, fmaxf(fmaxf(a.x, a.y), fmaxf(a.z, a.w)));
        mx = fmaxf(mx, fmaxf(fmaxf(b.x, b.y), fmaxf(b.z, b.w)));
        mx = fmaxf(mx, fmaxf(fmaxf(c.x, c.y), fmaxf(c.z, c.w)));
        mx = fmaxf(mx, fmaxf(fmaxf(d.x, d.y), fmaxf(d.z, d.w)));
    }
    float s = (s0 + s1) + (s2 + s3);
#pragma unroll
    for (int o = 16; o > 0; o >>= 1) {
        s  += __shfl_down_sync(0xffffffffu, s, o);
        mn = fminf(mn, __shfl_down_sync(0xffffffffu, mn, o));
        mx = fmaxf(mx, __shfl_down_sync(0xffffffffu, mx, o));
    }
    if (lane == 0) {
        g_mean[gw] = s * (1.0f / HW);
        g_min[gw]  = mn;
        g_max[gw]  = mx;
    }
}

// ------------------------------------------------------------------
// Kernel 2: SE MLP + hardsigmoid scale per (b,c), and per-sample
// min/max of out = scale*x (scale>=0 => min(scale*x)=scale*min(x)).
// ------------------------------------------------------------------
__global__ void k_se(const float* __restrict__ w1, const float* __restrict__ b1,
                     const float* __restrict__ w2, const float* __restrict__ b2) {
    int b = blockIdx.x, t = threadIdx.x;
    __shared__ float pooled[CC];
    __shared__ float hsh[CS];

    pooled[t] = g_mean[b * CC + t];
    __syncthreads();

    if (t < CS) {
        float acc = b1[t];
#pragma unroll 8
        for (int c = 0; c < CC; c++) acc = fmaf(pooled[c], w1[t * CC + c], acc);
        hsh[t] = fmaxf(acc, 0.f);
    }
    __syncthreads();

    float acc = b2[t];
#pragma unroll 8
    for (int s = 0; s < CS; s++) acc = fmaf(hsh[s], w2[t * CS + s], acc);
    float sc = fminf(fmaxf(acc / 6.0f + 0.5f, 0.f), 1.f);   // hardsigmoid
    g_scale[b * CC + t] = sc;

    float mn = sc * g_min[b * CC + t];
    float mx = sc * g_max[b * CC + t];
#pragma unroll
    for (int o = 16; o > 0; o >>= 1) {
        mn = fminf(mn, __shfl_down_sync(0xffffffffu, mn, o));
        mx = fmaxf(mx, __shfl_down_sync(0xffffffffu, mx, o));
    }
    __shared__ float sh_mn[8], sh_mx[8];
    int w = t >> 5, l = t & 31;
    if (l == 0) { sh_mn[w] = mn; sh_mx[w] = mx; }
    __syncthreads();
    if (t == 0) {
        float MN = CUDART_INF_F, MX = -CUDART_INF_F;
#pragma unroll
        for (int i = 0; i < 8; i++) { MN = fminf(MN, sh_mn[i]); MX = fmaxf(MX, sh_mx[i]); }
        g_smin[b] = MN;
        g_smax[b] = MX;
    }
}

// ------------------------------------------------------------------
// Kernel 3: per-cluster segment min/max + EMA + quant params.
// Staged through shared memory (fast version from R12, ~2us).
// ------------------------------------------------------------------
__global__ void k_cluster(const float* __restrict__ act_range,
                          const int* __restrict__ scl) {
    __shared__ float smn[BB], smx[BB];
    __shared__ int   scls[BB];
    __shared__ float cs[NC], cz[NC];
    int t = threadIdx.x;   // 64 threads

    smn[t]  = g_smin[t];
    smx[t]  = g_smax[t];
    scls[t] = scl[t];
    __syncthreads();

    if (t < NC) {
        float mn = CUDART_INF_F, mx = -CUDART_INF_F;  // JAX segment identities
#pragma unroll
        for (int b = 0; b < BB; b++) {
            if (scls[b] == t) {
                mn = fminf(mn, smn[b]);
                mx = fmaxf(mx, smx[b]);
            }
        }
        float nm = act_range[t * 2 + 0] * 0.995f + mn * 0.005f;
        float nx = act_range[t * 2 + 1] * 0.995f + mx * 0.005f;
        float s = (nx - nm) / 255.0f;
        float z = -rintf(__fdiv_rn(nm, s));
        cs[t] = s;
        cz[t] = z;
    }
    __syncthreads();
    {
        int k = scls[t];
        g_s[t] = cs[k];
        g_z[t] = cz[k];
    }
}

// ------------------------------------------------------------------
// Kernel 4: streaming fake-quant, REVERSED block order: the first
// scheduled blocks process the highest channels — exactly the part
// of x that k_stat read last and is still L2-resident. Stores are
// evict-first so they don't churn the resident x lines.
// ------------------------------------------------------------------
__global__ void __launch_bounds__(256) k_quant(const float* __restrict__ x,
                                               float* __restrict__ out) {
    int nb = (BB * CC * HW / 4) / 256;                 // 65536 blocks
    int i  = (nb - 1 - blockIdx.x) * 256 + threadIdx.x;  // reversed float4 index
    int bc = i >> 10;        // HW/4 = 1024 float4 per channel
    int b  = bc >> 8;        // CC = 256 channels per sample
    float sc = __ldg(&g_scale[bc]);
    float s  = __ldg(&g_s[b]);
    float z  = __ldg(&g_z[b]);

    float4 v = reinterpret_cast<const float4*>(x)[i];
    float4 r;
#define QUANT(a, o)                                                          \
    {                                                                        \
        float ov = sc * (a);                                                 \
        float q  = fminf(fmaxf(rintf(__fdiv_rn(ov, s) + z), 0.f), 255.f);    \
        (o) = (q - z) * s;                                                   \
    }
    QUANT(v.x, r.x)
    QUANT(v.y, r.y)
    QUANT(v.z, r.z)
    QUANT(v.w, r.w)
#undef QUANT
    __stcs(reinterpret_cast<float4*>(out) + i, r);
}

extern "C" void kernel_launch(void* const* d_in, const int* in_sizes, int n_in,
                              void* d_out, int out_size) {
    const float* x         = (const float*)d_in[0];
    const float* w1        = (const float*)d_in[1];
    const float* b1        = (const float*)d_in[2];
    const float* w2        = (const float*)d_in[3];
    const float* b2        = (const float*)d_in[4];
    const float* act_range = (const float*)d_in[5];
    const int*   scl       = (const int*)d_in[6];
    float* out = (float*)d_out;

    // k_stat: warp-per-channel, 8 warps/block, batches of 4 loads (R9 best)
    k_stat<<<(BB * CC) / 8, 256>>>(x);
    k_se<<<BB, 256>>>(w1, b1, w2, b2);
    k_cluster<<<1, 64>>>(act_range, scl);
    // k_quant: reversed traversal to harvest L2-resident tail of x
    k_quant<<<(BB * CC * HW / 4) / 256, 256>>>(x, out);
}